// round 8
// baseline (speedup 1.0000x reference)
#include <cuda_runtime.h>
#include <cuda_fp16.h>
#include <cstdint>

// Problem constants (fixed by the reference).
#define BB 4
#define CC 64
#define TT 8
#define HH 128
#define WW 128
#define DG 8
#define CG 8            // channels per deformable group = CC/DG
#define HW (HH*WW)      // 16384
#define THW (TT*HH*WW)  // 131072

// Bit-cast helper.
__device__ __forceinline__ unsigned h2_to_u(__half2 h) {
    union { __half2 h; unsigned u; } c; c.h = h; return c.u;
}
__device__ __forceinline__ __half2 u_to_h2(unsigned u) {
    union { unsigned u; __half2 h; } c; c.u = u; return c.h;
}

// Channel-last fp16 scratch: xT[b][g][t][h][w][c8] (16 B per pixel-group).
__device__ __half g_xT[(size_t)BB * DG * TT * HH * WW * CG];
// Sampled values (fp32) for the general-weight path.
__device__ float g_samp[(size_t)BB * DG * TT * HW * CG];

// Flag: 0 if weight==Identity and bias==0 (fast path), 1 otherwise.
__device__ int g_general;

// Transpose [B,C,T,H,W] fp32 -> [B,G,T,H,W,C8] fp16.
// One block per (b,g,t,h-pair). 256 threads.
__global__ __launch_bounds__(256, 8)
void transpose_kernel(const float* __restrict__ x,
                      const float* __restrict__ wgt,
                      const float* __restrict__ bias) {
    __shared__ float s[2][CG][WW + 4];
    __shared__ int sbad;

    if (blockIdx.x == 0) {
        if (threadIdx.x == 0) sbad = 0;
        __syncthreads();
        int bad = 0;
        for (int i = threadIdx.x; i < CC * CC; i += 256) {
            float e = ((i >> 6) == (i & 63)) ? 1.0f : 0.0f;
            if (wgt[i] != e) bad = 1;
        }
        if (threadIdx.x < CC && bias[threadIdx.x] != 0.0f) bad = 1;
        if (bad) atomicOr(&sbad, 1);
        __syncthreads();
        if (threadIdx.x == 0) g_general = sbad;
        __syncthreads();
    }

    const int n  = blockIdx.x;             // ((b*DG+g)*TT+t)*64 + h2
    const int h2 = n & 63;                 // h pair index
    const int t  = (n >> 6) & 7;
    const int g  = (n >> 9) & 7;
    const int b  = n >> 12;

    const int warp = threadIdx.x >> 5;     // channel within group
    const int lane = threadIdx.x & 31;

#pragma unroll
    for (int r = 0; r < 2; r++) {
        const float* src = x + ((size_t)(b * CC + g * CG + warp) * TT + t) * HW
                             + (size_t)(h2 * 2 + r) * WW;
        float4 v = ((const float4*)src)[lane];
        s[r][warp][lane * 4 + 0] = v.x;
        s[r][warp][lane * 4 + 1] = v.y;
        s[r][warp][lane * 4 + 2] = v.z;
        s[r][warp][lane * 4 + 3] = v.w;
    }
    __syncthreads();

    const int r = threadIdx.x >> 7;        // row within pair
    const int w = threadIdx.x & 127;
    uint4 o;
    o.x = h2_to_u(__floats2half2_rn(s[r][0][w], s[r][1][w]));
    o.y = h2_to_u(__floats2half2_rn(s[r][2][w], s[r][3][w]));
    o.z = h2_to_u(__floats2half2_rn(s[r][4][w], s[r][5][w]));
    o.w = h2_to_u(__floats2half2_rn(s[r][6][w], s[r][7][w]));
    __half* dst = g_xT + ((size_t)(((b * DG + g) * TT + t) * HH + h2 * 2 + r)) * (WW * CG);
    ((uint4*)dst)[w] = o;
}

// Gather. One thread per pixel-group; 256 threads = 8h x 32w tile.
// 8 batched LDG.128 (4 (t,h) corners x 2 adjacent w-corners), fp32 FMA,
// full-warp coalesced stores.
__global__ __launch_bounds__(256, 4)
void deform_kernel(const float* __restrict__ off,
                   float* __restrict__ out) {
    const int n  = blockIdx.x;
    const int wt = n & 3;            // w tile (4)
    const int ht = (n >> 2) & 15;    // h tile (16)
    const int t  = (n >> 6) & 7;
    const int g  = (n >> 9) & 7;
    const int b  = n >> 12;

    const int wl = threadIdx.x & 31;
    const int hl = threadIdx.x >> 5;         // 0..7
    const int w  = (wt << 5) + wl;
    const int h  = (ht << 3) + hl;

    // offset layout [B, 3*DG, T, H, W]; channel = g*3 + {0,1,2}
    const int so = ((b * (3 * DG) + g * 3) * TT + t) * HW + h * WW + w;
    const float ot = off[so];
    const float oh = off[so + THW];
    const float ow = off[so + 2 * THW];

    const float gt = (float)t + ot;
    const float gh = (float)h + oh;
    const float gw = (float)w + ow;
    const float ftf = floorf(gt), fhf = floorf(gh), fwf = floorf(gw);
    const int   t0 = (int)ftf,    h0 = (int)fhf,    w0 = (int)fwf;
    const float dt = gt - ftf,    dh = gh - fhf,    dw = gw - fwf;

    float wta[2], whb[2], wwc[2];
    int   tca[2], hcb[2], wcc[2];
    wta[0] = (1.0f - dt) * (((unsigned)t0       < (unsigned)TT) ? 1.0f : 0.0f);
    wta[1] = dt          * (((unsigned)(t0 + 1) < (unsigned)TT) ? 1.0f : 0.0f);
    whb[0] = (1.0f - dh) * (((unsigned)h0       < (unsigned)HH) ? 1.0f : 0.0f);
    whb[1] = dh          * (((unsigned)(h0 + 1) < (unsigned)HH) ? 1.0f : 0.0f);
    wwc[0] = (1.0f - dw) * (((unsigned)w0       < (unsigned)WW) ? 1.0f : 0.0f);
    wwc[1] = dw          * (((unsigned)(w0 + 1) < (unsigned)WW) ? 1.0f : 0.0f);
    tca[0] = min(TT - 1, max(0, t0));
    tca[1] = min(TT - 1, max(0, t0 + 1));
    hcb[0] = min(HH - 1, max(0, h0));
    hcb[1] = min(HH - 1, max(0, h0 + 1));
    wcc[0] = min(WW - 1, max(0, w0));
    wcc[1] = min(WW - 1, max(0, w0 + 1));

    const __half* bg = g_xT + (size_t)(b * DG + g) * THW * CG;

    // Batch all 8 independent 16 B loads for MLP.
    uint4 u[2][2], v[2][2];
#pragma unroll
    for (int a = 0; a < 2; a++) {
#pragma unroll
        for (int b2 = 0; b2 < 2; b2++) {
            const uint4* row =
                (const uint4*)(bg + (size_t)(tca[a] * HH + hcb[b2]) * (WW * CG));
            u[a][b2] = __ldg(row + wcc[0]);
            v[a][b2] = __ldg(row + wcc[1]);
        }
    }

    float acc0 = 0.f, acc1 = 0.f, acc2 = 0.f, acc3 = 0.f;
    float acc4 = 0.f, acc5 = 0.f, acc6 = 0.f, acc7 = 0.f;
#pragma unroll
    for (int a = 0; a < 2; a++) {
#pragma unroll
        for (int b2 = 0; b2 < 2; b2++) {
            const float wab = wta[a] * whb[b2];
            const float wc0 = wab * wwc[0];
            const float wc1 = wab * wwc[1];
            {
                float2 f0 = __half22float2(u_to_h2(u[a][b2].x));
                float2 f1 = __half22float2(u_to_h2(u[a][b2].y));
                float2 f2 = __half22float2(u_to_h2(u[a][b2].z));
                float2 f3 = __half22float2(u_to_h2(u[a][b2].w));
                acc0 = fmaf(wc0, f0.x, acc0); acc1 = fmaf(wc0, f0.y, acc1);
                acc2 = fmaf(wc0, f1.x, acc2); acc3 = fmaf(wc0, f1.y, acc3);
                acc4 = fmaf(wc0, f2.x, acc4); acc5 = fmaf(wc0, f2.y, acc5);
                acc6 = fmaf(wc0, f3.x, acc6); acc7 = fmaf(wc0, f3.y, acc7);
            }
            {
                float2 f0 = __half22float2(u_to_h2(v[a][b2].x));
                float2 f1 = __half22float2(u_to_h2(v[a][b2].y));
                float2 f2 = __half22float2(u_to_h2(v[a][b2].z));
                float2 f3 = __half22float2(u_to_h2(v[a][b2].w));
                acc0 = fmaf(wc1, f0.x, acc0); acc1 = fmaf(wc1, f0.y, acc1);
                acc2 = fmaf(wc1, f1.x, acc2); acc3 = fmaf(wc1, f1.y, acc3);
                acc4 = fmaf(wc1, f2.x, acc4); acc5 = fmaf(wc1, f2.y, acc5);
                acc6 = fmaf(wc1, f3.x, acc6); acc7 = fmaf(wc1, f3.y, acc7);
            }
        }
    }

    if (!g_general) {
        // Identity weight, zero bias: sampled IS the output.
        const size_t ob = ((size_t)(b * CC + g * CG) * TT + t) * HW
                        + (size_t)h * WW + w;
        out[ob]         = acc0;
        out[ob + THW]   = acc1;
        out[ob + 2*THW] = acc2;
        out[ob + 3*THW] = acc3;
        out[ob + 4*THW] = acc4;
        out[ob + 5*THW] = acc5;
        out[ob + 6*THW] = acc6;
        out[ob + 7*THW] = acc7;
    } else {
        float* dst = g_samp + ((size_t)(b * DG + g) * THW
                     + (size_t)t * HW + (size_t)h * WW + w) * CG;
        ((float4*)dst)[0] = make_float4(acc0, acc1, acc2, acc3);
        ((float4*)dst)[1] = make_float4(acc4, acc5, acc6, acc7);
    }
}

// General 1x1x1 conv path (early-exits when weight is identity).
__global__ __launch_bounds__(256, 4)
void conv_kernel(const float* __restrict__ wgt,
                 const float* __restrict__ bias,
                 float* __restrict__ out) {
    if (!g_general) return;
    const int p = blockIdx.x * 256 + threadIdx.x;   // pixel in [0, B*THW)
    const int b = p / THW;
    const int r = p - b * THW;

    float sv[CC];
#pragma unroll
    for (int g = 0; g < DG; g++) {
        const float* src = g_samp + ((size_t)(b * DG + g) * THW + r) * CG;
#pragma unroll
        for (int c = 0; c < CG; c++) sv[g * CG + c] = src[c];
    }
#pragma unroll 4
    for (int o = 0; o < CC; o++) {
        float a = bias[o];
#pragma unroll 16
        for (int c = 0; c < CC; c++)
            a = fmaf(wgt[o * CC + c], sv[c], a);
        out[(size_t)(b * CC + o) * THW + r] = a;
    }
}

extern "C" void kernel_launch(void* const* d_in, const int* in_sizes, int n_in,
                              void* d_out, int out_size) {
    const float* x    = (const float*)d_in[0];
    const float* off  = (const float*)d_in[1];
    const float* wgt  = (const float*)d_in[2];
    const float* bias = (const float*)d_in[3];
    float* out = (float*)d_out;

    const int ntrans = BB * DG * TT * (HH / 2);    // 16384
    transpose_kernel<<<ntrans, 256>>>(x, wgt, bias);

    const int nblocks = BB * DG * TT * 16 * 4;     // 16384
    deform_kernel<<<nblocks, 256>>>(off, out);

    conv_kernel<<<(BB * THW) / 256, 256>>>(wgt, bias, out);
}

// round 9
// speedup vs baseline: 1.0454x; 1.0454x over previous
#include <cuda_runtime.h>
#include <cuda_fp16.h>
#include <cstdint>

// Problem constants (fixed by the reference).
#define BB 4
#define CC 64
#define TT 8
#define HH 128
#define WW 128
#define DG 8
#define CG 8            // channels per deformable group = CC/DG
#define HW (HH*WW)      // 16384
#define THW (TT*HH*WW)  // 131072

// Bit-cast helpers.
__device__ __forceinline__ unsigned h2_to_u(__half2 h) {
    union { __half2 h; unsigned u; } c; c.h = h; return c.u;
}
__device__ __forceinline__ __half2 u_to_h2(unsigned u) {
    union { unsigned u; __half2 h; } c; c.u = u; return c.h;
}

// Channel-last fp16 scratch: xT[b][g][t][h][w][c8] (16 B per pixel-group).
__device__ __half g_xT[(size_t)BB * DG * TT * HH * WW * CG];
// Sampled values (fp32) for the general-weight path.
__device__ float g_samp[(size_t)BB * DG * TT * HW * CG];

// Flag: 0 if weight==Identity and bias==0 (fast path), 1 otherwise.
__device__ int g_general;

// Transpose [B,C,T,H,W] fp32 -> [B,G,T,H,W,C8] fp16.
// One block per (b,g,t,h-pair). 256 threads.
__global__ __launch_bounds__(256, 8)
void transpose_kernel(const float* __restrict__ x,
                      const float* __restrict__ wgt,
                      const float* __restrict__ bias) {
    __shared__ float s[2][CG][WW + 4];
    __shared__ int sbad;

    if (blockIdx.x == 0) {
        if (threadIdx.x == 0) sbad = 0;
        __syncthreads();
        int bad = 0;
        for (int i = threadIdx.x; i < CC * CC; i += 256) {
            float e = ((i >> 6) == (i & 63)) ? 1.0f : 0.0f;
            if (wgt[i] != e) bad = 1;
        }
        if (threadIdx.x < CC && bias[threadIdx.x] != 0.0f) bad = 1;
        if (bad) atomicOr(&sbad, 1);
        __syncthreads();
        if (threadIdx.x == 0) g_general = sbad;
        __syncthreads();
    }

    const int n  = blockIdx.x;             // ((b*DG+g)*TT+t)*64 + h2
    const int h2 = n & 63;                 // h pair index
    const int t  = (n >> 6) & 7;
    const int g  = (n >> 9) & 7;
    const int b  = n >> 12;

    const int warp = threadIdx.x >> 5;     // channel within group
    const int lane = threadIdx.x & 31;

#pragma unroll
    for (int r = 0; r < 2; r++) {
        const float* src = x + ((size_t)(b * CC + g * CG + warp) * TT + t) * HW
                             + (size_t)(h2 * 2 + r) * WW;
        float4 v = ((const float4*)src)[lane];
        s[r][warp][lane * 4 + 0] = v.x;
        s[r][warp][lane * 4 + 1] = v.y;
        s[r][warp][lane * 4 + 2] = v.z;
        s[r][warp][lane * 4 + 3] = v.w;
    }
    __syncthreads();

    const int r = threadIdx.x >> 7;        // row within pair
    const int w = threadIdx.x & 127;
    uint4 o;
    o.x = h2_to_u(__floats2half2_rn(s[r][0][w], s[r][1][w]));
    o.y = h2_to_u(__floats2half2_rn(s[r][2][w], s[r][3][w]));
    o.z = h2_to_u(__floats2half2_rn(s[r][4][w], s[r][5][w]));
    o.w = h2_to_u(__floats2half2_rn(s[r][6][w], s[r][7][w]));
    __half* dst = g_xT + ((size_t)(((b * DG + g) * TT + t) * HH + h2 * 2 + r)) * (WW * CG);
    ((uint4*)dst)[w] = o;
}

// Gather. Block = (b, g, 8h x 32w tile), looping t = 0..7 internally so that
// consecutive t-iterations reuse overlapping t-plane rows from L1.
// 512 threads = 256 pixels x 2 w-corner threads (R7's best-measured shape).
// Lane layout: bit0 = w-corner, bits1-5 = w, bits6-8 = h.
__global__ __launch_bounds__(512, 2)
void deform_kernel(const float* __restrict__ off,
                   float* __restrict__ out) {
    const int n  = blockIdx.x;
    const int wt = n & 3;            // w tile (4)
    const int ht = (n >> 2) & 15;    // h tile (16)
    const int g  = (n >> 6) & 7;
    const int b  = n >> 9;

    const int wq = threadIdx.x & 1;          // w-corner select
    const int wl = (threadIdx.x >> 1) & 31;
    const int hl = threadIdx.x >> 6;         // 0..7
    const int w  = (wt << 5) + wl;
    const int h  = (ht << 3) + hl;

    const __half* bg  = g_xT + (size_t)(b * DG + g) * THW * CG;
    const int     so0 = ((b * (3 * DG) + g * 3) * TT) * HW + h * WW + w;

    for (int t = 0; t < TT; ++t) {
        // offset layout [B, 3*DG, T, H, W]; channel = g*3 + {0,1,2}
        const int so = so0 + t * HW;
        const float ot = off[so];
        const float oh = off[so + THW];
        const float ow = off[so + 2 * THW];

        const float gt = (float)t + ot;
        const float gh = (float)h + oh;
        const float gw = (float)w + ow;
        const float ftf = floorf(gt), fhf = floorf(gh), fwf = floorf(gw);
        const int   t0 = (int)ftf,    h0 = (int)fhf,    w0 = (int)fwf;
        const float dt = gt - ftf,    dh = gh - fhf,    dw = gw - fwf;

        float wta[2], whb[2];
        int   tca[2], hcb[2];
        wta[0] = (1.0f - dt) * (((unsigned)t0       < (unsigned)TT) ? 1.0f : 0.0f);
        wta[1] = dt          * (((unsigned)(t0 + 1) < (unsigned)TT) ? 1.0f : 0.0f);
        whb[0] = (1.0f - dh) * (((unsigned)h0       < (unsigned)HH) ? 1.0f : 0.0f);
        whb[1] = dh          * (((unsigned)(h0 + 1) < (unsigned)HH) ? 1.0f : 0.0f);
        tca[0] = min(TT - 1, max(0, t0));
        tca[1] = min(TT - 1, max(0, t0 + 1));
        hcb[0] = min(HH - 1, max(0, h0));
        hcb[1] = min(HH - 1, max(0, h0 + 1));

        // This thread's w-corner.
        const int   wcm = w0 + wq;
        const float wwq = (wq ? dw : (1.0f - dw))
                        * (((unsigned)wcm < (unsigned)WW) ? 1.0f : 0.0f);
        const int   wcc = min(WW - 1, max(0, wcm));

        // Batch the 4 independent 16 B loads (full 8 fp16 channels each).
        uint4 u[2][2];
#pragma unroll
        for (int a = 0; a < 2; a++) {
#pragma unroll
            for (int b2 = 0; b2 < 2; b2++) {
                const uint4* row =
                    (const uint4*)(bg + (size_t)(tca[a] * HH + hcb[b2]) * (WW * CG));
                u[a][b2] = __ldg(row + wcc);
            }
        }

        float acc0 = 0.f, acc1 = 0.f, acc2 = 0.f, acc3 = 0.f;
        float acc4 = 0.f, acc5 = 0.f, acc6 = 0.f, acc7 = 0.f;
#pragma unroll
        for (int a = 0; a < 2; a++) {
#pragma unroll
            for (int b2 = 0; b2 < 2; b2++) {
                const float wc = wta[a] * whb[b2] * wwq;
                float2 f0 = __half22float2(u_to_h2(u[a][b2].x));
                float2 f1 = __half22float2(u_to_h2(u[a][b2].y));
                float2 f2 = __half22float2(u_to_h2(u[a][b2].z));
                float2 f3 = __half22float2(u_to_h2(u[a][b2].w));
                acc0 = fmaf(wc, f0.x, acc0); acc1 = fmaf(wc, f0.y, acc1);
                acc2 = fmaf(wc, f1.x, acc2); acc3 = fmaf(wc, f1.y, acc3);
                acc4 = fmaf(wc, f2.x, acc4); acc5 = fmaf(wc, f2.y, acc5);
                acc6 = fmaf(wc, f3.x, acc6); acc7 = fmaf(wc, f3.y, acc7);
            }
        }

        // Combine the two w-corners (lane pairs differ only in bit0).
        acc0 += __shfl_xor_sync(0xFFFFFFFFu, acc0, 1);
        acc1 += __shfl_xor_sync(0xFFFFFFFFu, acc1, 1);
        acc2 += __shfl_xor_sync(0xFFFFFFFFu, acc2, 1);
        acc3 += __shfl_xor_sync(0xFFFFFFFFu, acc3, 1);
        acc4 += __shfl_xor_sync(0xFFFFFFFFu, acc4, 1);
        acc5 += __shfl_xor_sync(0xFFFFFFFFu, acc5, 1);
        acc6 += __shfl_xor_sync(0xFFFFFFFFu, acc6, 1);
        acc7 += __shfl_xor_sync(0xFFFFFFFFu, acc7, 1);

        if (wq == 0) {
            if (!g_general) {
                const size_t ob = ((size_t)(b * CC + g * CG) * TT + t) * HW
                                + (size_t)h * WW + w;
                out[ob]           = acc0;
                out[ob + THW]     = acc1;
                out[ob + 2*THW]   = acc2;
                out[ob + 3*THW]   = acc3;
                out[ob + 4*THW]   = acc4;
                out[ob + 5*THW]   = acc5;
                out[ob + 6*THW]   = acc6;
                out[ob + 7*THW]   = acc7;
            } else {
                float* dst = g_samp + ((size_t)(b * DG + g) * THW
                             + (size_t)t * HW + (size_t)h * WW + w) * CG;
                ((float4*)dst)[0] = make_float4(acc0, acc1, acc2, acc3);
                ((float4*)dst)[1] = make_float4(acc4, acc5, acc6, acc7);
            }
        }
    }
}

// General 1x1x1 conv path (early-exits when weight is identity).
__global__ __launch_bounds__(256, 4)
void conv_kernel(const float* __restrict__ wgt,
                 const float* __restrict__ bias,
                 float* __restrict__ out) {
    if (!g_general) return;
    const int p = blockIdx.x * 256 + threadIdx.x;   // pixel in [0, B*THW)
    const int b = p / THW;
    const int r = p - b * THW;

    float sv[CC];
#pragma unroll
    for (int g = 0; g < DG; g++) {
        const float* src = g_samp + ((size_t)(b * DG + g) * THW + r) * CG;
#pragma unroll
        for (int c = 0; c < CG; c++) sv[g * CG + c] = src[c];
    }
#pragma unroll 4
    for (int o = 0; o < CC; o++) {
        float a = bias[o];
#pragma unroll 16
        for (int c = 0; c < CC; c++)
            a = fmaf(wgt[o * CC + c], sv[c], a);
        out[(size_t)(b * CC + o) * THW + r] = a;
    }
}

extern "C" void kernel_launch(void* const* d_in, const int* in_sizes, int n_in,
                              void* d_out, int out_size) {
    const float* x    = (const float*)d_in[0];
    const float* off  = (const float*)d_in[1];
    const float* wgt  = (const float*)d_in[2];
    const float* bias = (const float*)d_in[3];
    float* out = (float*)d_out;

    const int ntrans = BB * DG * TT * (HH / 2);    // 16384
    transpose_kernel<<<ntrans, 256>>>(x, wgt, bias);

    const int nblocks = BB * DG * 16 * 4;          // 2048, loop t inside
    deform_kernel<<<nblocks, 512>>>(off, out);

    conv_kernel<<<(BB * THW) / 256, 256>>>(wgt, bias, out);
}

// round 10
// speedup vs baseline: 1.1604x; 1.1100x over previous
#include <cuda_runtime.h>
#include <cuda_fp16.h>
#include <cstdint>

// Problem constants (fixed by the reference).
#define BB 4
#define CC 64
#define TT 8
#define HH 128
#define WW 128
#define DG 8
#define CG 8            // channels per deformable group = CC/DG
#define HW (HH*WW)      // 16384
#define THW (TT*HH*WW)  // 131072

// Bit-cast helpers.
__device__ __forceinline__ unsigned h2_to_u(__half2 h) {
    union { __half2 h; unsigned u; } c; c.h = h; return c.u;
}
__device__ __forceinline__ __half2 u_to_h2(unsigned u) {
    union { unsigned u; __half2 h; } c; c.u = u; return c.h;
}

// Channel-last fp16 scratch: xT[b][g][t][h][w][c8] (16 B per pixel-group).
__device__ __half g_xT[(size_t)BB * DG * TT * HH * WW * CG];
// Sampled values (fp32) for the general-weight path.
__device__ float g_samp[(size_t)BB * DG * TT * HW * CG];

// Flag: 0 if weight==Identity and bias==0 (fast path), 1 otherwise.
__device__ int g_general;

// Transpose [B,C,T,H,W] fp32 -> [B,G,T,H,W,C8] fp16.
// One block per (b,g,t,h-pair). 256 threads.
__global__ __launch_bounds__(256, 8)
void transpose_kernel(const float* __restrict__ x,
                      const float* __restrict__ wgt,
                      const float* __restrict__ bias) {
    __shared__ float s[2][CG][WW + 4];
    __shared__ int sbad;

    if (blockIdx.x == 0) {
        if (threadIdx.x == 0) sbad = 0;
        __syncthreads();
        int bad = 0;
        for (int i = threadIdx.x; i < CC * CC; i += 256) {
            float e = ((i >> 6) == (i & 63)) ? 1.0f : 0.0f;
            if (wgt[i] != e) bad = 1;
        }
        if (threadIdx.x < CC && bias[threadIdx.x] != 0.0f) bad = 1;
        if (bad) atomicOr(&sbad, 1);
        __syncthreads();
        if (threadIdx.x == 0) g_general = sbad;
        __syncthreads();
    }

    const int n  = blockIdx.x;             // ((b*DG+g)*TT+t)*64 + h2
    const int h2 = n & 63;                 // h pair index
    const int t  = (n >> 6) & 7;
    const int g  = (n >> 9) & 7;
    const int b  = n >> 12;

    const int warp = threadIdx.x >> 5;     // channel within group
    const int lane = threadIdx.x & 31;

#pragma unroll
    for (int r = 0; r < 2; r++) {
        const float* src = x + ((size_t)(b * CC + g * CG + warp) * TT + t) * HW
                             + (size_t)(h2 * 2 + r) * WW;
        float4 v = ((const float4*)src)[lane];
        s[r][warp][lane * 4 + 0] = v.x;
        s[r][warp][lane * 4 + 1] = v.y;
        s[r][warp][lane * 4 + 2] = v.z;
        s[r][warp][lane * 4 + 3] = v.w;
    }
    __syncthreads();

    const int r = threadIdx.x >> 7;        // row within pair
    const int w = threadIdx.x & 127;
    uint4 o;
    o.x = h2_to_u(__floats2half2_rn(s[r][0][w], s[r][1][w]));
    o.y = h2_to_u(__floats2half2_rn(s[r][2][w], s[r][3][w]));
    o.z = h2_to_u(__floats2half2_rn(s[r][4][w], s[r][5][w]));
    o.w = h2_to_u(__floats2half2_rn(s[r][6][w], s[r][7][w]));
    __half* dst = g_xT + ((size_t)(((b * DG + g) * TT + t) * HH + h2 * 2 + r)) * (WW * CG);
    ((uint4*)dst)[w] = o;
}

// Gather. Block = (b, g, 8h x 32w tile), looping t = 0..7 internally.
// 512 threads = 256 pixels x 2 w-corner threads.
// Occupancy raised to 3 blocks/SM (48 warps) for latency hiding.
__global__ __launch_bounds__(512, 3)
void deform_kernel(const float* __restrict__ off,
                   float* __restrict__ out) {
    const int n  = blockIdx.x;
    const int wt = n & 3;            // w tile (4)
    const int ht = (n >> 2) & 15;    // h tile (16)
    const int g  = (n >> 6) & 7;
    const int b  = n >> 9;

    const int wq = threadIdx.x & 1;          // w-corner select
    const int wl = (threadIdx.x >> 1) & 31;
    const int hl = threadIdx.x >> 6;         // 0..7
    const int w  = (wt << 5) + wl;
    const int h  = (ht << 3) + hl;

    const __half* bg  = g_xT + (size_t)(b * DG + g) * THW * CG;
    const int     so0 = ((b * (3 * DG) + g * 3) * TT) * HW + h * WW + w;

    for (int t = 0; t < TT; ++t) {
        // offset layout [B, 3*DG, T, H, W]; channel = g*3 + {0,1,2}
        const int so = so0 + t * HW;
        const float ot = off[so];
        const float oh = off[so + THW];
        const float ow = off[so + 2 * THW];

        const float gt = (float)t + ot;
        const float gh = (float)h + oh;
        const float gw = (float)w + ow;
        const float ftf = floorf(gt), fhf = floorf(gh), fwf = floorf(gw);
        const int   t0 = (int)ftf,    h0 = (int)fhf,    w0 = (int)fwf;
        const float dt = gt - ftf,    dh = gh - fhf,    dw = gw - fwf;

        float wta[2], whb[2];
        int   tca[2], hcb[2];
        wta[0] = (1.0f - dt) * (((unsigned)t0       < (unsigned)TT) ? 1.0f : 0.0f);
        wta[1] = dt          * (((unsigned)(t0 + 1) < (unsigned)TT) ? 1.0f : 0.0f);
        whb[0] = (1.0f - dh) * (((unsigned)h0       < (unsigned)HH) ? 1.0f : 0.0f);
        whb[1] = dh          * (((unsigned)(h0 + 1) < (unsigned)HH) ? 1.0f : 0.0f);
        tca[0] = min(TT - 1, max(0, t0));
        tca[1] = min(TT - 1, max(0, t0 + 1));
        hcb[0] = min(HH - 1, max(0, h0));
        hcb[1] = min(HH - 1, max(0, h0 + 1));

        // This thread's w-corner.
        const int   wcm = w0 + wq;
        const float wwq = (wq ? dw : (1.0f - dw))
                        * (((unsigned)wcm < (unsigned)WW) ? 1.0f : 0.0f);
        const int   wcc = min(WW - 1, max(0, wcm));

        // Batch the 4 independent 16 B loads (full 8 fp16 channels each).
        uint4 u[2][2];
#pragma unroll
        for (int a = 0; a < 2; a++) {
#pragma unroll
            for (int b2 = 0; b2 < 2; b2++) {
                const uint4* row =
                    (const uint4*)(bg + (size_t)(tca[a] * HH + hcb[b2]) * (WW * CG));
                u[a][b2] = __ldg(row + wcc);
            }
        }

        float acc0 = 0.f, acc1 = 0.f, acc2 = 0.f, acc3 = 0.f;
        float acc4 = 0.f, acc5 = 0.f, acc6 = 0.f, acc7 = 0.f;
#pragma unroll
        for (int a = 0; a < 2; a++) {
#pragma unroll
            for (int b2 = 0; b2 < 2; b2++) {
                const float wc = wta[a] * whb[b2] * wwq;
                float2 f0 = __half22float2(u_to_h2(u[a][b2].x));
                float2 f1 = __half22float2(u_to_h2(u[a][b2].y));
                float2 f2 = __half22float2(u_to_h2(u[a][b2].z));
                float2 f3 = __half22float2(u_to_h2(u[a][b2].w));
                acc0 = fmaf(wc, f0.x, acc0); acc1 = fmaf(wc, f0.y, acc1);
                acc2 = fmaf(wc, f1.x, acc2); acc3 = fmaf(wc, f1.y, acc3);
                acc4 = fmaf(wc, f2.x, acc4); acc5 = fmaf(wc, f2.y, acc5);
                acc6 = fmaf(wc, f3.x, acc6); acc7 = fmaf(wc, f3.y, acc7);
            }
        }

        // Combine the two w-corners (lane pairs differ only in bit0).
        acc0 += __shfl_xor_sync(0xFFFFFFFFu, acc0, 1);
        acc1 += __shfl_xor_sync(0xFFFFFFFFu, acc1, 1);
        acc2 += __shfl_xor_sync(0xFFFFFFFFu, acc2, 1);
        acc3 += __shfl_xor_sync(0xFFFFFFFFu, acc3, 1);
        acc4 += __shfl_xor_sync(0xFFFFFFFFu, acc4, 1);
        acc5 += __shfl_xor_sync(0xFFFFFFFFu, acc5, 1);
        acc6 += __shfl_xor_sync(0xFFFFFFFFu, acc6, 1);
        acc7 += __shfl_xor_sync(0xFFFFFFFFu, acc7, 1);

        if (wq == 0) {
            if (!g_general) {
                const size_t ob = ((size_t)(b * CC + g * CG) * TT + t) * HW
                                + (size_t)h * WW + w;
                out[ob]           = acc0;
                out[ob + THW]     = acc1;
                out[ob + 2*THW]   = acc2;
                out[ob + 3*THW]   = acc3;
                out[ob + 4*THW]   = acc4;
                out[ob + 5*THW]   = acc5;
                out[ob + 6*THW]   = acc6;
                out[ob + 7*THW]   = acc7;
            } else {
                float* dst = g_samp + ((size_t)(b * DG + g) * THW
                             + (size_t)t * HW + (size_t)h * WW + w) * CG;
                ((float4*)dst)[0] = make_float4(acc0, acc1, acc2, acc3);
                ((float4*)dst)[1] = make_float4(acc4, acc5, acc6, acc7);
            }
        }
    }
}

// General 1x1x1 conv path (early-exits when weight is identity).
__global__ __launch_bounds__(256, 4)
void conv_kernel(const float* __restrict__ wgt,
                 const float* __restrict__ bias,
                 float* __restrict__ out) {
    if (!g_general) return;
    const int p = blockIdx.x * 256 + threadIdx.x;   // pixel in [0, B*THW)
    const int b = p / THW;
    const int r = p - b * THW;

    float sv[CC];
#pragma unroll
    for (int g = 0; g < DG; g++) {
        const float* src = g_samp + ((size_t)(b * DG + g) * THW + r) * CG;
#pragma unroll
        for (int c = 0; c < CG; c++) sv[g * CG + c] = src[c];
    }
#pragma unroll 4
    for (int o = 0; o < CC; o++) {
        float a = bias[o];
#pragma unroll 16
        for (int c = 0; c < CC; c++)
            a = fmaf(wgt[o * CC + c], sv[c], a);
        out[(size_t)(b * CC + o) * THW + r] = a;
    }
}

extern "C" void kernel_launch(void* const* d_in, const int* in_sizes, int n_in,
                              void* d_out, int out_size) {
    const float* x    = (const float*)d_in[0];
    const float* off  = (const float*)d_in[1];
    const float* wgt  = (const float*)d_in[2];
    const float* bias = (const float*)d_in[3];
    float* out = (float*)d_out;

    const int ntrans = BB * DG * TT * (HH / 2);    // 16384
    transpose_kernel<<<ntrans, 256>>>(x, wgt, bias);

    const int nblocks = BB * DG * 16 * 4;          // 2048, loop t inside
    deform_kernel<<<nblocks, 512>>>(off, out);

    conv_kernel<<<(BB * THW) / 256, 256>>>(wgt, bias, out);
}

// round 11
// speedup vs baseline: 1.1885x; 1.0242x over previous
#include <cuda_runtime.h>
#include <cuda_fp16.h>
#include <cstdint>

// Problem constants (fixed by the reference).
#define BB 4
#define CC 64
#define TT 8
#define HH 128
#define WW 128
#define DG 8
#define CG 8            // channels per deformable group = CC/DG
#define HW (HH*WW)      // 16384
#define THW (TT*HH*WW)  // 131072

// Bit-cast helpers.
__device__ __forceinline__ unsigned h2_to_u(__half2 h) {
    union { __half2 h; unsigned u; } c; c.h = h; return c.u;
}
__device__ __forceinline__ __half2 u_to_h2(unsigned u) {
    union { unsigned u; __half2 h; } c; c.u = u; return c.h;
}

// Channel-last fp16 scratch: xT[b][g][t][h][w][c8] (16 B per pixel-group).
__device__ __half g_xT[(size_t)BB * DG * TT * HH * WW * CG];
// Sampled values (fp32) for the general-weight path.
__device__ float g_samp[(size_t)BB * DG * TT * HW * CG];

// Flag: 0 if weight==Identity and bias==0 (fast path), 1 otherwise.
__device__ int g_general;

// Transpose [B,C,T,H,W] fp32 -> [B,G,T,H,W,C8] fp16.
// One block per (b,g,t,h-pair). 256 threads.
__global__ __launch_bounds__(256, 8)
void transpose_kernel(const float* __restrict__ x,
                      const float* __restrict__ wgt,
                      const float* __restrict__ bias) {
    __shared__ float s[2][CG][WW + 4];
    __shared__ int sbad;

    if (blockIdx.x == 0) {
        if (threadIdx.x == 0) sbad = 0;
        __syncthreads();
        int bad = 0;
        for (int i = threadIdx.x; i < CC * CC; i += 256) {
            float e = ((i >> 6) == (i & 63)) ? 1.0f : 0.0f;
            if (wgt[i] != e) bad = 1;
        }
        if (threadIdx.x < CC && bias[threadIdx.x] != 0.0f) bad = 1;
        if (bad) atomicOr(&sbad, 1);
        __syncthreads();
        if (threadIdx.x == 0) g_general = sbad;
        __syncthreads();
    }

    const int n  = blockIdx.x;             // ((b*DG+g)*TT+t)*64 + h2
    const int h2 = n & 63;                 // h pair index
    const int t  = (n >> 6) & 7;
    const int g  = (n >> 9) & 7;
    const int b  = n >> 12;

    const int warp = threadIdx.x >> 5;     // channel within group
    const int lane = threadIdx.x & 31;

#pragma unroll
    for (int r = 0; r < 2; r++) {
        const float* src = x + ((size_t)(b * CC + g * CG + warp) * TT + t) * HW
                             + (size_t)(h2 * 2 + r) * WW;
        float4 v = ((const float4*)src)[lane];
        s[r][warp][lane * 4 + 0] = v.x;
        s[r][warp][lane * 4 + 1] = v.y;
        s[r][warp][lane * 4 + 2] = v.z;
        s[r][warp][lane * 4 + 3] = v.w;
    }
    __syncthreads();

    const int r = threadIdx.x >> 7;        // row within pair
    const int w = threadIdx.x & 127;
    uint4 o;
    o.x = h2_to_u(__floats2half2_rn(s[r][0][w], s[r][1][w]));
    o.y = h2_to_u(__floats2half2_rn(s[r][2][w], s[r][3][w]));
    o.z = h2_to_u(__floats2half2_rn(s[r][4][w], s[r][5][w]));
    o.w = h2_to_u(__floats2half2_rn(s[r][6][w], s[r][7][w]));
    __half* dst = g_xT + ((size_t)(((b * DG + g) * TT + t) * HH + h2 * 2 + r)) * (WW * CG);
    ((uint4*)dst)[w] = o;
}

// Gather. Block = (b, g, 8h x 32w tile), looping t = 0..7 internally.
// 512 threads = 256 pixels x 2 w-corner threads; 3 blocks/SM (48 warps).
// Offset loads for t+1 are software-pipelined so their latency overlaps the
// gather+FMA work of iteration t.
__global__ __launch_bounds__(512, 3)
void deform_kernel(const float* __restrict__ off,
                   float* __restrict__ out) {
    const int n  = blockIdx.x;
    const int wt = n & 3;            // w tile (4)
    const int ht = (n >> 2) & 15;    // h tile (16)
    const int g  = (n >> 6) & 7;
    const int b  = n >> 9;

    const int wq = threadIdx.x & 1;          // w-corner select
    const int wl = (threadIdx.x >> 1) & 31;
    const int hl = threadIdx.x >> 6;         // 0..7
    const int w  = (wt << 5) + wl;
    const int h  = (ht << 3) + hl;

    const __half* bg  = g_xT + (size_t)(b * DG + g) * THW * CG;
    const int     so0 = ((b * (3 * DG) + g * 3) * TT) * HW + h * WW + w;

    // Prologue: load offsets for t=0.
    float ot = off[so0];
    float oh = off[so0 + THW];
    float ow = off[so0 + 2 * THW];

    for (int t = 0; t < TT; ++t) {
        const float gt = (float)t + ot;
        const float gh = (float)h + oh;
        const float gw = (float)w + ow;

        // Pipelined load of next iteration's offsets (overlaps this
        // iteration's gather latency).
        if (t + 1 < TT) {
            const int so = so0 + (t + 1) * HW;
            ot = off[so];
            oh = off[so + THW];
            ow = off[so + 2 * THW];
        }

        const float ftf = floorf(gt), fhf = floorf(gh), fwf = floorf(gw);
        const int   t0 = (int)ftf,    h0 = (int)fhf,    w0 = (int)fwf;
        const float dt = gt - ftf,    dh = gh - fhf,    dw = gw - fwf;

        float wta[2], whb[2];
        int   tca[2], hcb[2];
        wta[0] = (1.0f - dt) * (((unsigned)t0       < (unsigned)TT) ? 1.0f : 0.0f);
        wta[1] = dt          * (((unsigned)(t0 + 1) < (unsigned)TT) ? 1.0f : 0.0f);
        whb[0] = (1.0f - dh) * (((unsigned)h0       < (unsigned)HH) ? 1.0f : 0.0f);
        whb[1] = dh          * (((unsigned)(h0 + 1) < (unsigned)HH) ? 1.0f : 0.0f);
        tca[0] = min(TT - 1, max(0, t0));
        tca[1] = min(TT - 1, max(0, t0 + 1));
        hcb[0] = min(HH - 1, max(0, h0));
        hcb[1] = min(HH - 1, max(0, h0 + 1));

        // This thread's w-corner.
        const int   wcm = w0 + wq;
        const float wwq = (wq ? dw : (1.0f - dw))
                        * (((unsigned)wcm < (unsigned)WW) ? 1.0f : 0.0f);
        const int   wcc = min(WW - 1, max(0, wcm));

        // Batch the 4 independent 16 B loads (full 8 fp16 channels each).
        uint4 u[2][2];
#pragma unroll
        for (int a = 0; a < 2; a++) {
#pragma unroll
            for (int b2 = 0; b2 < 2; b2++) {
                const uint4* row =
                    (const uint4*)(bg + (size_t)(tca[a] * HH + hcb[b2]) * (WW * CG));
                u[a][b2] = __ldg(row + wcc);
            }
        }

        float acc0 = 0.f, acc1 = 0.f, acc2 = 0.f, acc3 = 0.f;
        float acc4 = 0.f, acc5 = 0.f, acc6 = 0.f, acc7 = 0.f;
#pragma unroll
        for (int a = 0; a < 2; a++) {
#pragma unroll
            for (int b2 = 0; b2 < 2; b2++) {
                const float wc = wta[a] * whb[b2] * wwq;
                float2 f0 = __half22float2(u_to_h2(u[a][b2].x));
                float2 f1 = __half22float2(u_to_h2(u[a][b2].y));
                float2 f2 = __half22float2(u_to_h2(u[a][b2].z));
                float2 f3 = __half22float2(u_to_h2(u[a][b2].w));
                acc0 = fmaf(wc, f0.x, acc0); acc1 = fmaf(wc, f0.y, acc1);
                acc2 = fmaf(wc, f1.x, acc2); acc3 = fmaf(wc, f1.y, acc3);
                acc4 = fmaf(wc, f2.x, acc4); acc5 = fmaf(wc, f2.y, acc5);
                acc6 = fmaf(wc, f3.x, acc6); acc7 = fmaf(wc, f3.y, acc7);
            }
        }

        // Combine the two w-corners (lane pairs differ only in bit0).
        acc0 += __shfl_xor_sync(0xFFFFFFFFu, acc0, 1);
        acc1 += __shfl_xor_sync(0xFFFFFFFFu, acc1, 1);
        acc2 += __shfl_xor_sync(0xFFFFFFFFu, acc2, 1);
        acc3 += __shfl_xor_sync(0xFFFFFFFFu, acc3, 1);
        acc4 += __shfl_xor_sync(0xFFFFFFFFu, acc4, 1);
        acc5 += __shfl_xor_sync(0xFFFFFFFFu, acc5, 1);
        acc6 += __shfl_xor_sync(0xFFFFFFFFu, acc6, 1);
        acc7 += __shfl_xor_sync(0xFFFFFFFFu, acc7, 1);

        if (wq == 0) {
            if (!g_general) {
                const size_t ob = ((size_t)(b * CC + g * CG) * TT + t) * HW
                                + (size_t)h * WW + w;
                out[ob]           = acc0;
                out[ob + THW]     = acc1;
                out[ob + 2*THW]   = acc2;
                out[ob + 3*THW]   = acc3;
                out[ob + 4*THW]   = acc4;
                out[ob + 5*THW]   = acc5;
                out[ob + 6*THW]   = acc6;
                out[ob + 7*THW]   = acc7;
            } else {
                float* dst = g_samp + ((size_t)(b * DG + g) * THW
                             + (size_t)t * HW + (size_t)h * WW + w) * CG;
                ((float4*)dst)[0] = make_float4(acc0, acc1, acc2, acc3);
                ((float4*)dst)[1] = make_float4(acc4, acc5, acc6, acc7);
            }
        }
    }
}

// General 1x1x1 conv path (early-exits when weight is identity).
__global__ __launch_bounds__(256, 4)
void conv_kernel(const float* __restrict__ wgt,
                 const float* __restrict__ bias,
                 float* __restrict__ out) {
    if (!g_general) return;
    const int p = blockIdx.x * 256 + threadIdx.x;   // pixel in [0, B*THW)
    const int b = p / THW;
    const int r = p - b * THW;

    float sv[CC];
#pragma unroll
    for (int g = 0; g < DG; g++) {
        const float* src = g_samp + ((size_t)(b * DG + g) * THW + r) * CG;
#pragma unroll
        for (int c = 0; c < CG; c++) sv[g * CG + c] = src[c];
    }
#pragma unroll 4
    for (int o = 0; o < CC; o++) {
        float a = bias[o];
#pragma unroll 16
        for (int c = 0; c < CC; c++)
            a = fmaf(wgt[o * CC + c], sv[c], a);
        out[(size_t)(b * CC + o) * THW + r] = a;
    }
}

extern "C" void kernel_launch(void* const* d_in, const int* in_sizes, int n_in,
                              void* d_out, int out_size) {
    const float* x    = (const float*)d_in[0];
    const float* off  = (const float*)d_in[1];
    const float* wgt  = (const float*)d_in[2];
    const float* bias = (const float*)d_in[3];
    float* out = (float*)d_out;

    const int ntrans = BB * DG * TT * (HH / 2);    // 16384
    transpose_kernel<<<ntrans, 256>>>(x, wgt, bias);

    const int nblocks = BB * DG * 16 * 4;          // 2048, loop t inside
    deform_kernel<<<nblocks, 512>>>(off, out);

    conv_kernel<<<(BB * THW) / 256, 256>>>(wgt, bias, out);
}

// round 12
// speedup vs baseline: 1.2287x; 1.0339x over previous
#include <cuda_runtime.h>
#include <cuda_fp16.h>
#include <cstdint>

// Problem constants (fixed by the reference).
#define BB 4
#define CC 64
#define TT 8
#define HH 128
#define WW 128
#define DG 8
#define CG 8            // channels per deformable group = CC/DG
#define HW (HH*WW)      // 16384
#define THW (TT*HH*WW)  // 131072

// Bit-cast helpers.
__device__ __forceinline__ unsigned h2_to_u(__half2 h) {
    union { __half2 h; unsigned u; } c; c.h = h; return c.u;
}
__device__ __forceinline__ __half2 u_to_h2(unsigned u) {
    union { unsigned u; __half2 h; } c; c.u = u; return c.h;
}

// Channel-last fp16 scratch: xT[b][g][t][h][w][c8] (16 B per pixel-group).
__device__ __half g_xT[(size_t)BB * DG * TT * HH * WW * CG];
// Sampled values (fp32) for the general-weight path.
__device__ float g_samp[(size_t)BB * DG * TT * HW * CG];

// Flag: 0 if weight==Identity and bias==0 (fast path), 1 otherwise.
__device__ int g_general;

// Transpose [B,C,T,H,W] fp32 -> [B,G,T,H,W,C8] fp16. No smem: one thread per
// output pixel-group; 8 coalesced LDG.32 (one per channel plane) + 1 STG.128.
// Block 0 additionally computes g_general from weight/bias.
__global__ __launch_bounds__(256, 8)
void transpose_kernel(const float* __restrict__ x,
                      const float* __restrict__ wgt,
                      const float* __restrict__ bias) {
    if (blockIdx.x == 0) {
        __shared__ int sbad;
        if (threadIdx.x == 0) sbad = 0;
        __syncthreads();
        int bad = 0;
        for (int i = threadIdx.x; i < CC * CC; i += 256) {
            float e = ((i >> 6) == (i & 63)) ? 1.0f : 0.0f;
            if (wgt[i] != e) bad = 1;
        }
        if (threadIdx.x < CC && bias[threadIdx.x] != 0.0f) bad = 1;
        if (bad) atomicOr(&sbad, 1);
        __syncthreads();
        if (threadIdx.x == 0) g_general = sbad;
        __syncthreads();
    }

    // Linear index over [B][DG][T][H][W].
    const int p  = blockIdx.x * 256 + threadIdx.x;
    const int hw = p & (HW - 1);
    const int t  = (p >> 14) & 7;
    const int g  = (p >> 17) & 7;
    const int b  = p >> 20;

    const float* src = x + ((size_t)(b * CC + g * CG) * TT + t) * HW + hw;
    float v0 = src[0];
    float v1 = src[THW];
    float v2 = src[2 * THW];
    float v3 = src[3 * THW];
    float v4 = src[4 * THW];
    float v5 = src[5 * THW];
    float v6 = src[6 * THW];
    float v7 = src[7 * THW];

    uint4 o;
    o.x = h2_to_u(__floats2half2_rn(v0, v1));
    o.y = h2_to_u(__floats2half2_rn(v2, v3));
    o.z = h2_to_u(__floats2half2_rn(v4, v5));
    o.w = h2_to_u(__floats2half2_rn(v6, v7));
    ((uint4*)g_xT)[p] = o;
}

// Gather. Block = (b, g, 8h x 32w tile), looping t = 0..7 internally.
// 512 threads = 256 pixels x 2 w-corner threads; target 4 blocks/SM (64 warps).
// Register diet: 32-bit row byte-offsets, gathers issued 2+2.
__global__ __launch_bounds__(512, 4)
void deform_kernel(const float* __restrict__ off,
                   float* __restrict__ out) {
    const int n  = blockIdx.x;
    const int wt = n & 3;            // w tile (4)
    const int ht = (n >> 2) & 15;    // h tile (16)
    const int g  = (n >> 6) & 7;
    const int b  = n >> 9;

    const int wq = threadIdx.x & 1;          // w-corner select
    const int wl = (threadIdx.x >> 1) & 31;
    const int hl = threadIdx.x >> 6;         // 0..7
    const int w  = (wt << 5) + wl;
    const int h  = (ht << 3) + hl;

    const char* bg  = (const char*)(g_xT + (size_t)(b * DG + g) * THW * CG);
    const int   so0 = ((b * (3 * DG) + g * 3) * TT) * HW + h * WW + w;

    // Prologue: load offsets for t=0.
    float ot = off[so0];
    float oh = off[so0 + THW];
    float ow = off[so0 + 2 * THW];

    for (int t = 0; t < TT; ++t) {
        const float gt = (float)t + ot;
        const float gh = (float)h + oh;
        const float gw = (float)w + ow;

        // Pipelined load of next iteration's offsets.
        if (t + 1 < TT) {
            const int so = so0 + (t + 1) * HW;
            ot = off[so];
            oh = off[so + THW];
            ow = off[so + 2 * THW];
        }

        const float ftf = floorf(gt), fhf = floorf(gh), fwf = floorf(gw);
        const int   t0 = (int)ftf,    h0 = (int)fhf,    w0 = (int)fwf;
        const float dt = gt - ftf,    dh = gh - fhf,    dw = gw - fwf;

        float wta0 = (1.0f - dt) * (((unsigned)t0       < (unsigned)TT) ? 1.0f : 0.0f);
        float wta1 = dt          * (((unsigned)(t0 + 1) < (unsigned)TT) ? 1.0f : 0.0f);
        float whb0 = (1.0f - dh) * (((unsigned)h0       < (unsigned)HH) ? 1.0f : 0.0f);
        float whb1 = dh          * (((unsigned)(h0 + 1) < (unsigned)HH) ? 1.0f : 0.0f);
        const int tc0 = min(TT - 1, max(0, t0));
        const int tc1 = min(TT - 1, max(0, t0 + 1));
        const int hc0 = min(HH - 1, max(0, h0));
        const int hc1 = min(HH - 1, max(0, h0 + 1));

        // This thread's w-corner.
        const int   wcm = w0 + wq;
        const float wwq = (wq ? dw : (1.0f - dw))
                        * (((unsigned)wcm < (unsigned)WW) ? 1.0f : 0.0f);
        const unsigned wb = (unsigned)min(WW - 1, max(0, wcm)) * 16u;

        // 32-bit row byte-offsets within this (b,g) slice (< 2 MB).
        const unsigned RB = (unsigned)(WW * CG * 2);   // bytes per row
        const unsigned r00 = (unsigned)(tc0 * HH + hc0) * RB + wb;
        const unsigned r01 = (unsigned)(tc0 * HH + hc1) * RB + wb;
        const unsigned r10 = (unsigned)(tc1 * HH + hc0) * RB + wb;
        const unsigned r11 = (unsigned)(tc1 * HH + hc1) * RB + wb;

        float acc0 = 0.f, acc1 = 0.f, acc2 = 0.f, acc3 = 0.f;
        float acc4 = 0.f, acc5 = 0.f, acc6 = 0.f, acc7 = 0.f;

        // t-corner 0: two gathers, then FMA.
        {
            uint4 ua = __ldg((const uint4*)(bg + r00));
            uint4 ub = __ldg((const uint4*)(bg + r01));
            const float wc_a = wta0 * whb0 * wwq;
            const float wc_b = wta0 * whb1 * wwq;
            float2 f;
            f = __half22float2(u_to_h2(ua.x)); acc0 = fmaf(wc_a, f.x, acc0); acc1 = fmaf(wc_a, f.y, acc1);
            f = __half22float2(u_to_h2(ua.y)); acc2 = fmaf(wc_a, f.x, acc2); acc3 = fmaf(wc_a, f.y, acc3);
            f = __half22float2(u_to_h2(ua.z)); acc4 = fmaf(wc_a, f.x, acc4); acc5 = fmaf(wc_a, f.y, acc5);
            f = __half22float2(u_to_h2(ua.w)); acc6 = fmaf(wc_a, f.x, acc6); acc7 = fmaf(wc_a, f.y, acc7);
            f = __half22float2(u_to_h2(ub.x)); acc0 = fmaf(wc_b, f.x, acc0); acc1 = fmaf(wc_b, f.y, acc1);
            f = __half22float2(u_to_h2(ub.y)); acc2 = fmaf(wc_b, f.x, acc2); acc3 = fmaf(wc_b, f.y, acc3);
            f = __half22float2(u_to_h2(ub.z)); acc4 = fmaf(wc_b, f.x, acc4); acc5 = fmaf(wc_b, f.y, acc5);
            f = __half22float2(u_to_h2(ub.w)); acc6 = fmaf(wc_b, f.x, acc6); acc7 = fmaf(wc_b, f.y, acc7);
        }
        // t-corner 1: two gathers, then FMA.
        {
            uint4 ua = __ldg((const uint4*)(bg + r10));
            uint4 ub = __ldg((const uint4*)(bg + r11));
            const float wc_a = wta1 * whb0 * wwq;
            const float wc_b = wta1 * whb1 * wwq;
            float2 f;
            f = __half22float2(u_to_h2(ua.x)); acc0 = fmaf(wc_a, f.x, acc0); acc1 = fmaf(wc_a, f.y, acc1);
            f = __half22float2(u_to_h2(ua.y)); acc2 = fmaf(wc_a, f.x, acc2); acc3 = fmaf(wc_a, f.y, acc3);
            f = __half22float2(u_to_h2(ua.z)); acc4 = fmaf(wc_a, f.x, acc4); acc5 = fmaf(wc_a, f.y, acc5);
            f = __half22float2(u_to_h2(ua.w)); acc6 = fmaf(wc_a, f.x, acc6); acc7 = fmaf(wc_a, f.y, acc7);
            f = __half22float2(u_to_h2(ub.x)); acc0 = fmaf(wc_b, f.x, acc0); acc1 = fmaf(wc_b, f.y, acc1);
            f = __half22float2(u_to_h2(ub.y)); acc2 = fmaf(wc_b, f.x, acc2); acc3 = fmaf(wc_b, f.y, acc3);
            f = __half22float2(u_to_h2(ub.z)); acc4 = fmaf(wc_b, f.x, acc4); acc5 = fmaf(wc_b, f.y, acc5);
            f = __half22float2(u_to_h2(ub.w)); acc6 = fmaf(wc_b, f.x, acc6); acc7 = fmaf(wc_b, f.y, acc7);
        }

        // Combine the two w-corners (lane pairs differ only in bit0).
        acc0 += __shfl_xor_sync(0xFFFFFFFFu, acc0, 1);
        acc1 += __shfl_xor_sync(0xFFFFFFFFu, acc1, 1);
        acc2 += __shfl_xor_sync(0xFFFFFFFFu, acc2, 1);
        acc3 += __shfl_xor_sync(0xFFFFFFFFu, acc3, 1);
        acc4 += __shfl_xor_sync(0xFFFFFFFFu, acc4, 1);
        acc5 += __shfl_xor_sync(0xFFFFFFFFu, acc5, 1);
        acc6 += __shfl_xor_sync(0xFFFFFFFFu, acc6, 1);
        acc7 += __shfl_xor_sync(0xFFFFFFFFu, acc7, 1);

        if (wq == 0) {
            if (!g_general) {
                const size_t ob = ((size_t)(b * CC + g * CG) * TT + t) * HW
                                + (size_t)h * WW + w;
                out[ob]           = acc0;
                out[ob + THW]     = acc1;
                out[ob + 2*THW]   = acc2;
                out[ob + 3*THW]   = acc3;
                out[ob + 4*THW]   = acc4;
                out[ob + 5*THW]   = acc5;
                out[ob + 6*THW]   = acc6;
                out[ob + 7*THW]   = acc7;
            } else {
                float* dst = g_samp + ((size_t)(b * DG + g) * THW
                             + (size_t)t * HW + (size_t)h * WW + w) * CG;
                ((float4*)dst)[0] = make_float4(acc0, acc1, acc2, acc3);
                ((float4*)dst)[1] = make_float4(acc4, acc5, acc6, acc7);
            }
        }
    }
}

// General 1x1x1 conv path (early-exits when weight is identity).
__global__ __launch_bounds__(256, 4)
void conv_kernel(const float* __restrict__ wgt,
                 const float* __restrict__ bias,
                 float* __restrict__ out) {
    if (!g_general) return;
    const int p = blockIdx.x * 256 + threadIdx.x;   // pixel in [0, B*THW)
    const int b = p / THW;
    const int r = p - b * THW;

    float sv[CC];
#pragma unroll
    for (int g = 0; g < DG; g++) {
        const float* src = g_samp + ((size_t)(b * DG + g) * THW + r) * CG;
#pragma unroll
        for (int c = 0; c < CG; c++) sv[g * CG + c] = src[c];
    }
#pragma unroll 4
    for (int o = 0; o < CC; o++) {
        float a = bias[o];
#pragma unroll 16
        for (int c = 0; c < CC; c++)
            a = fmaf(wgt[o * CC + c], sv[c], a);
        out[(size_t)(b * CC + o) * THW + r] = a;
    }
}

extern "C" void kernel_launch(void* const* d_in, const int* in_sizes, int n_in,
                              void* d_out, int out_size) {
    const float* x    = (const float*)d_in[0];
    const float* off  = (const float*)d_in[1];
    const float* wgt  = (const float*)d_in[2];
    const float* bias = (const float*)d_in[3];
    float* out = (float*)d_out;

    const int ntrans = (BB * DG * THW) / 256;      // 16384
    transpose_kernel<<<ntrans, 256>>>(x, wgt, bias);

    const int nblocks = BB * DG * 16 * 4;          // 2048, loop t inside
    deform_kernel<<<nblocks, 512>>>(off, out);

    conv_kernel<<<(BB * THW) / 256, 256>>>(wgt, bias, out);
}

// round 13
// speedup vs baseline: 1.2528x; 1.0196x over previous
#include <cuda_runtime.h>
#include <cuda_fp16.h>
#include <cstdint>

// Problem constants (fixed by the reference).
#define BB 4
#define CC 64
#define TT 8
#define HH 128
#define WW 128
#define DG 8
#define CG 8            // channels per deformable group = CC/DG
#define HW (HH*WW)      // 16384
#define THW (TT*HH*WW)  // 131072

// Bit-cast helpers.
__device__ __forceinline__ unsigned h2_to_u(__half2 h) {
    union { __half2 h; unsigned u; } c; c.h = h; return c.u;
}
__device__ __forceinline__ __half2 u_to_h2(unsigned u) {
    union { unsigned u; __half2 h; } c; c.u = u; return c.h;
}

// Channel-last fp16 scratch: xT[b][g][t][h][w][c8] (16 B per pixel-group).
__device__ __half g_xT[(size_t)BB * DG * TT * HH * WW * CG];
// Sampled values (fp32) for the general-weight path.
__device__ float g_samp[(size_t)BB * DG * TT * HW * CG];

// Flag: 0 if weight==Identity and bias==0 (fast path), 1 otherwise.
__device__ int g_general;

// Transpose [B,C,T,H,W] fp32 -> [B,G,T,H,W,C8] fp16. No smem: one thread per
// output pixel-group; 8 coalesced streaming LDG.32 + 1 STG.128.
// Block 0 additionally computes g_general from weight/bias.
__global__ __launch_bounds__(256, 8)
void transpose_kernel(const float* __restrict__ x,
                      const float* __restrict__ wgt,
                      const float* __restrict__ bias) {
    if (blockIdx.x == 0) {
        __shared__ int sbad;
        if (threadIdx.x == 0) sbad = 0;
        __syncthreads();
        int bad = 0;
        for (int i = threadIdx.x; i < CC * CC; i += 256) {
            float e = ((i >> 6) == (i & 63)) ? 1.0f : 0.0f;
            if (wgt[i] != e) bad = 1;
        }
        if (threadIdx.x < CC && bias[threadIdx.x] != 0.0f) bad = 1;
        if (bad) atomicOr(&sbad, 1);
        __syncthreads();
        if (threadIdx.x == 0) g_general = sbad;
        __syncthreads();
    }

    // Linear index over [B][DG][T][H][W].
    const int p  = blockIdx.x * 256 + threadIdx.x;
    const int hw = p & (HW - 1);
    const int t  = (p >> 14) & 7;
    const int g  = (p >> 17) & 7;
    const int b  = p >> 20;

    // Streaming reads: x is read exactly once; don't pollute L2 with it.
    const float* src = x + ((size_t)(b * CC + g * CG) * TT + t) * HW + hw;
    float v0 = __ldcs(src);
    float v1 = __ldcs(src + THW);
    float v2 = __ldcs(src + 2 * THW);
    float v3 = __ldcs(src + 3 * THW);
    float v4 = __ldcs(src + 4 * THW);
    float v5 = __ldcs(src + 5 * THW);
    float v6 = __ldcs(src + 6 * THW);
    float v7 = __ldcs(src + 7 * THW);

    uint4 o;
    o.x = h2_to_u(__floats2half2_rn(v0, v1));
    o.y = h2_to_u(__floats2half2_rn(v2, v3));
    o.z = h2_to_u(__floats2half2_rn(v4, v5));
    o.w = h2_to_u(__floats2half2_rn(v6, v7));
    ((uint4*)g_xT)[p] = o;    // normal store: xT is the next kernel's working set
}

// Gather. Block = (b, g, 8h x 32w tile), looping t = 0..7 internally.
// 512 threads = 256 pixels x 2 w-corner threads; 4 blocks/SM target.
// off reads and out writes use streaming (.cs) policy so xT stays L2-resident.
__global__ __launch_bounds__(512, 4)
void deform_kernel(const float* __restrict__ off,
                   float* __restrict__ out) {
    const int n  = blockIdx.x;
    const int wt = n & 3;            // w tile (4)
    const int ht = (n >> 2) & 15;    // h tile (16)
    const int g  = (n >> 6) & 7;
    const int b  = n >> 9;

    const int wq = threadIdx.x & 1;          // w-corner select
    const int wl = (threadIdx.x >> 1) & 31;
    const int hl = threadIdx.x >> 6;         // 0..7
    const int w  = (wt << 5) + wl;
    const int h  = (ht << 3) + hl;

    const char* bg  = (const char*)(g_xT + (size_t)(b * DG + g) * THW * CG);
    const int   so0 = ((b * (3 * DG) + g * 3) * TT) * HW + h * WW + w;

    // Prologue: load offsets for t=0 (streaming — read once).
    float ot = __ldcs(off + so0);
    float oh = __ldcs(off + so0 + THW);
    float ow = __ldcs(off + so0 + 2 * THW);

    for (int t = 0; t < TT; ++t) {
        const float gt = (float)t + ot;
        const float gh = (float)h + oh;
        const float gw = (float)w + ow;

        // Pipelined load of next iteration's offsets.
        if (t + 1 < TT) {
            const int so = so0 + (t + 1) * HW;
            ot = __ldcs(off + so);
            oh = __ldcs(off + so + THW);
            ow = __ldcs(off + so + 2 * THW);
        }

        const float ftf = floorf(gt), fhf = floorf(gh), fwf = floorf(gw);
        const int   t0 = (int)ftf,    h0 = (int)fhf,    w0 = (int)fwf;
        const float dt = gt - ftf,    dh = gh - fhf,    dw = gw - fwf;

        float wta0 = (1.0f - dt) * (((unsigned)t0       < (unsigned)TT) ? 1.0f : 0.0f);
        float wta1 = dt          * (((unsigned)(t0 + 1) < (unsigned)TT) ? 1.0f : 0.0f);
        float whb0 = (1.0f - dh) * (((unsigned)h0       < (unsigned)HH) ? 1.0f : 0.0f);
        float whb1 = dh          * (((unsigned)(h0 + 1) < (unsigned)HH) ? 1.0f : 0.0f);
        const int tc0 = min(TT - 1, max(0, t0));
        const int tc1 = min(TT - 1, max(0, t0 + 1));
        const int hc0 = min(HH - 1, max(0, h0));
        const int hc1 = min(HH - 1, max(0, h0 + 1));

        // This thread's w-corner.
        const int   wcm = w0 + wq;
        const float wwq = (wq ? dw : (1.0f - dw))
                        * (((unsigned)wcm < (unsigned)WW) ? 1.0f : 0.0f);
        const unsigned wb = (unsigned)min(WW - 1, max(0, wcm)) * 16u;

        // 32-bit row byte-offsets within this (b,g) slice (< 2 MB).
        const unsigned RB = (unsigned)(WW * CG * 2);   // bytes per row
        const unsigned r00 = (unsigned)(tc0 * HH + hc0) * RB + wb;
        const unsigned r01 = (unsigned)(tc0 * HH + hc1) * RB + wb;
        const unsigned r10 = (unsigned)(tc1 * HH + hc0) * RB + wb;
        const unsigned r11 = (unsigned)(tc1 * HH + hc1) * RB + wb;

        float acc0 = 0.f, acc1 = 0.f, acc2 = 0.f, acc3 = 0.f;
        float acc4 = 0.f, acc5 = 0.f, acc6 = 0.f, acc7 = 0.f;

        // t-corner 0: two gathers, then FMA.
        {
            uint4 ua = __ldg((const uint4*)(bg + r00));
            uint4 ub = __ldg((const uint4*)(bg + r01));
            const float wc_a = wta0 * whb0 * wwq;
            const float wc_b = wta0 * whb1 * wwq;
            float2 f;
            f = __half22float2(u_to_h2(ua.x)); acc0 = fmaf(wc_a, f.x, acc0); acc1 = fmaf(wc_a, f.y, acc1);
            f = __half22float2(u_to_h2(ua.y)); acc2 = fmaf(wc_a, f.x, acc2); acc3 = fmaf(wc_a, f.y, acc3);
            f = __half22float2(u_to_h2(ua.z)); acc4 = fmaf(wc_a, f.x, acc4); acc5 = fmaf(wc_a, f.y, acc5);
            f = __half22float2(u_to_h2(ua.w)); acc6 = fmaf(wc_a, f.x, acc6); acc7 = fmaf(wc_a, f.y, acc7);
            f = __half22float2(u_to_h2(ub.x)); acc0 = fmaf(wc_b, f.x, acc0); acc1 = fmaf(wc_b, f.y, acc1);
            f = __half22float2(u_to_h2(ub.y)); acc2 = fmaf(wc_b, f.x, acc2); acc3 = fmaf(wc_b, f.y, acc3);
            f = __half22float2(u_to_h2(ub.z)); acc4 = fmaf(wc_b, f.x, acc4); acc5 = fmaf(wc_b, f.y, acc5);
            f = __half22float2(u_to_h2(ub.w)); acc6 = fmaf(wc_b, f.x, acc6); acc7 = fmaf(wc_b, f.y, acc7);
        }
        // t-corner 1: two gathers, then FMA.
        {
            uint4 ua = __ldg((const uint4*)(bg + r10));
            uint4 ub = __ldg((const uint4*)(bg + r11));
            const float wc_a = wta1 * whb0 * wwq;
            const float wc_b = wta1 * whb1 * wwq;
            float2 f;
            f = __half22float2(u_to_h2(ua.x)); acc0 = fmaf(wc_a, f.x, acc0); acc1 = fmaf(wc_a, f.y, acc1);
            f = __half22float2(u_to_h2(ua.y)); acc2 = fmaf(wc_a, f.x, acc2); acc3 = fmaf(wc_a, f.y, acc3);
            f = __half22float2(u_to_h2(ua.z)); acc4 = fmaf(wc_a, f.x, acc4); acc5 = fmaf(wc_a, f.y, acc5);
            f = __half22float2(u_to_h2(ua.w)); acc6 = fmaf(wc_a, f.x, acc6); acc7 = fmaf(wc_a, f.y, acc7);
            f = __half22float2(u_to_h2(ub.x)); acc0 = fmaf(wc_b, f.x, acc0); acc1 = fmaf(wc_b, f.y, acc1);
            f = __half22float2(u_to_h2(ub.y)); acc2 = fmaf(wc_b, f.x, acc2); acc3 = fmaf(wc_b, f.y, acc3);
            f = __half22float2(u_to_h2(ub.z)); acc4 = fmaf(wc_b, f.x, acc4); acc5 = fmaf(wc_b, f.y, acc5);
            f = __half22float2(u_to_h2(ub.w)); acc6 = fmaf(wc_b, f.x, acc6); acc7 = fmaf(wc_b, f.y, acc7);
        }

        // Combine the two w-corners (lane pairs differ only in bit0).
        acc0 += __shfl_xor_sync(0xFFFFFFFFu, acc0, 1);
        acc1 += __shfl_xor_sync(0xFFFFFFFFu, acc1, 1);
        acc2 += __shfl_xor_sync(0xFFFFFFFFu, acc2, 1);
        acc3 += __shfl_xor_sync(0xFFFFFFFFu, acc3, 1);
        acc4 += __shfl_xor_sync(0xFFFFFFFFu, acc4, 1);
        acc5 += __shfl_xor_sync(0xFFFFFFFFu, acc5, 1);
        acc6 += __shfl_xor_sync(0xFFFFFFFFu, acc6, 1);
        acc7 += __shfl_xor_sync(0xFFFFFFFFu, acc7, 1);

        if (wq == 0) {
            if (!g_general) {
                // Streaming stores: out is write-once, keep it out of L2.
                float* ob = out + ((size_t)(b * CC + g * CG) * TT + t) * HW
                                + (size_t)h * WW + w;
                __stcs(ob,           acc0);
                __stcs(ob + THW,     acc1);
                __stcs(ob + 2*THW,   acc2);
                __stcs(ob + 3*THW,   acc3);
                __stcs(ob + 4*THW,   acc4);
                __stcs(ob + 5*THW,   acc5);
                __stcs(ob + 6*THW,   acc6);
                __stcs(ob + 7*THW,   acc7);
            } else {
                float* dst = g_samp + ((size_t)(b * DG + g) * THW
                             + (size_t)t * HW + (size_t)h * WW + w) * CG;
                ((float4*)dst)[0] = make_float4(acc0, acc1, acc2, acc3);
                ((float4*)dst)[1] = make_float4(acc4, acc5, acc6, acc7);
            }
        }
    }
}

// General 1x1x1 conv path (early-exits when weight is identity).
// Small grid (256 blocks); each thread handles 8 pixels so the fast-path
// early-exit costs almost nothing.
__global__ __launch_bounds__(256, 4)
void conv_kernel(const float* __restrict__ wgt,
                 const float* __restrict__ bias,
                 float* __restrict__ out) {
    if (!g_general) return;
    const int base = (blockIdx.x * 256 + threadIdx.x) * 8;
#pragma unroll 1
    for (int k = 0; k < 8; k++) {
        const int p = base + k;                 // pixel in [0, B*THW)
        const int b = p / THW;
        const int r = p - b * THW;

        float sv[CC];
#pragma unroll
        for (int g = 0; g < DG; g++) {
            const float* src = g_samp + ((size_t)(b * DG + g) * THW + r) * CG;
#pragma unroll
            for (int c = 0; c < CG; c++) sv[g * CG + c] = src[c];
        }
#pragma unroll 4
        for (int o = 0; o < CC; o++) {
            float a = bias[o];
#pragma unroll 16
            for (int c = 0; c < CC; c++)
                a = fmaf(wgt[o * CC + c], sv[c], a);
            out[(size_t)(b * CC + o) * THW + r] = a;
        }
    }
}

extern "C" void kernel_launch(void* const* d_in, const int* in_sizes, int n_in,
                              void* d_out, int out_size) {
    const float* x    = (const float*)d_in[0];
    const float* off  = (const float*)d_in[1];
    const float* wgt  = (const float*)d_in[2];
    const float* bias = (const float*)d_in[3];
    float* out = (float*)d_out;

    const int ntrans = (BB * DG * THW) / 256;      // 16384
    transpose_kernel<<<ntrans, 256>>>(x, wgt, bias);

    const int nblocks = BB * DG * 16 * 4;          // 2048, loop t inside
    deform_kernel<<<nblocks, 512>>>(off, out);

    conv_kernel<<<(BB * THW) / (256 * 8), 256>>>(wgt, bias, out);
}